// round 10
// baseline (speedup 1.0000x reference)
#include <cuda_runtime.h>
#include <cstdint>

// out[r,c] = sign(r) * x_real[r,c]   (real-part coercion; rel_err=0.0 confirmed)
// sign(r) = -1 iff ( popc(r & (r>>1)) + ((r & 1) & (r >> 12)) ) is odd.
//
// R10: complete the MLP ladder with plain LDG/STG (no cache hints — R7/R8
// showed .cs costs ~4% DRAM throughput on sm_103a).
//   MLP=1: 38.5us / 72.8%   MLP=2: 35.6us / 75.5%   MLP=4: this round.

static constexpr unsigned N_WIRES = 13;

__device__ __forceinline__ float row_sign(unsigned row) {
    unsigned parity = __popc(row & (row >> 1)) + ((row & 1u) & (row >> (N_WIRES - 1)));
    return (parity & 1u) ? -1.0f : 1.0f;
}

// Exact cover: each block owns 1024 consecutive float4s; thread t handles
// base + t + {0,256,512,768}. No bounds checks (host guarantees divisibility).
__global__ __launch_bounds__(256) void cz_real_v4(
    const float4* __restrict__ xr,
    float4* __restrict__ out,
    unsigned row_shift)        // log2(batch/4)
{
    unsigned i0 = blockIdx.x * 1024u + threadIdx.x;
    unsigned i1 = i0 + 256u;
    unsigned i2 = i0 + 512u;
    unsigned i3 = i0 + 768u;

    float4 v0 = xr[i0];
    float4 v1 = xr[i1];
    float4 v2 = xr[i2];
    float4 v3 = xr[i3];

    float s0 = row_sign(i0 >> row_shift);
    float s1 = row_sign(i1 >> row_shift);
    float s2 = row_sign(i2 >> row_shift);
    float s3 = row_sign(i3 >> row_shift);

    v0.x *= s0; v0.y *= s0; v0.z *= s0; v0.w *= s0;
    v1.x *= s1; v1.y *= s1; v1.z *= s1; v1.w *= s1;
    v2.x *= s2; v2.y *= s2; v2.z *= s2; v2.w *= s2;
    v3.x *= s3; v3.y *= s3; v3.z *= s3; v3.w *= s3;

    out[i0] = v0;
    out[i1] = v1;
    out[i2] = v2;
    out[i3] = v3;
}

// Scalar path: tail [start, n) or full problem for odd shapes/alignment.
__global__ __launch_bounds__(256) void cz_real_scalar(
    const float* __restrict__ xr,
    float* __restrict__ out,
    unsigned start, unsigned n_elems, unsigned batch)
{
    unsigned i = start + blockIdx.x * 256u + threadIdx.x;
    if (i >= n_elems) return;
    float s = row_sign(i / batch);
    out[i] = s * xr[i];
}

extern "C" void kernel_launch(void* const* d_in, const int* in_sizes, int n_in,
                              void* d_out, int out_size)
{
    if (n_in < 1) return;
    const void* xr = d_in[0];

    unsigned E = (unsigned)out_size;
    if ((unsigned)in_sizes[0] < E) E = (unsigned)in_sizes[0];
    if (E == 0) return;

    unsigned batch = E >> N_WIRES;          // columns (4096 nominally)
    if (batch == 0) batch = 1;

    bool pow2_batch4 = (batch % 4u == 0) &&
                       (((batch / 4u) & (batch / 4u - 1u)) == 0);
    bool vec_ok =
        (((uintptr_t)xr) % 16u == 0) &&
        (((uintptr_t)d_out) % 16u == 0) &&
        pow2_batch4 && (E % 4u == 0);

    if (vec_ok) {
        unsigned vpr = batch / 4u;                    // 1024 nominally
        unsigned row_shift = 0;
        while ((1u << row_shift) < vpr) row_shift++;  // log2 (vpr is pow2)

        unsigned n_vec = E / 4u;                      // 2^23 nominally
        unsigned full_blocks = n_vec / 1024u;         // 8192 nominally
        if (full_blocks)
            cz_real_v4<<<full_blocks, 256>>>(
                (const float4*)xr, (float4*)d_out, row_shift);

        unsigned done = full_blocks * 1024u * 4u;     // floats covered
        if (done < E)                                  // tail (none nominally)
            cz_real_scalar<<<((E - done) + 255u) / 256u, 256>>>(
                (const float*)xr, (float*)d_out, done, E, batch);
    } else {
        cz_real_scalar<<<(E + 255u) / 256u, 256>>>(
            (const float*)xr, (float*)d_out, 0, E, batch);
    }
}